// round 17
// baseline (speedup 1.0000x reference)
#include <cuda_runtime.h>
#include <math.h>

#define NB 32
#define NK 4
#define NC 256
#define HW 1024
#define MID 32
#define KC 1280   // (K+1)*C
#define EPSV 1e-5f

#define NBLK 128        // 8192 rows / 64 per block (round-8 proven layout)
#define BC_PER_BLK 64
#define SROWS 8         // rows stashed in smem per block (multiple of 4)
#define STASKS (SROWS*5)  // 40 tensor-rows * 4KB = 160KB dynamic smem

// Scratch (device globals — no allocation allowed). Barrier counters return
// to 0 every launch (graph-replay safe, proven rounds 5-12).
__device__ float g_feats[NB * KC];
__device__ unsigned g_cnt1;
__device__ unsigned g_cnt2;

extern __shared__ float4 stash4[];   // STASKS * 256 float4 = 163840 B

// ---------------------------------------------------------------------------
// Fused persistent kernel, 128 blocks x 1024 threads.
// Key invariant (round-12 lesson): phase-1 temporal read order must be
// ROW-ascending so the reverse-row phase 2 walks L2 recency correctly.
//   Phase 1: round-8 task striding (task = warp + 32*it, row = task/5).
//            Tasks 0..39 (rows 0-7) stashed to smem via .cs loads; the
//            stash predicate is compile-time except one warp-uniform test
//            at it==1.
//   Grid barrier (self-resetting).
//   Gates:   h[b] + sigmoid/softmax (one b per block since 64 | 256).
//   Phase 2: REVERSE row order. it<2 (rows 0-7) from smem (compile-time
//            branch); other rows via __ldcs (consumed once — evict-first
//            fill protects not-yet-visited resident rows). Stores .cs.
// ---------------------------------------------------------------------------
__global__ __launch_bounds__(1024, 1) void fused_kernel(
    const float* __restrict__ y,
    const float* __restrict__ x0,
    const float* __restrict__ x1,
    const float* __restrict__ x2,
    const float* __restrict__ x3,
    const float* __restrict__ conv1_w,   // [MID, KC]
    const float* __restrict__ bn_gamma,
    const float* __restrict__ bn_beta,
    const float* __restrict__ bn_mean,
    const float* __restrict__ bn_var,
    const float* __restrict__ conv2_w,   // [KC, MID]
    const float* __restrict__ conv2_b,   // [KC]
    float* __restrict__ out)
{
    __shared__ float h_s[MID];
    __shared__ float sw1[BC_PER_BLK];
    __shared__ float sw2[NK][BC_PER_BLK];

    const int tid  = threadIdx.x;
    const int warp = tid >> 5;
    const int lane = tid & 31;
    const int s    = blockIdx.x * BC_PER_BLK;   // first bc row of this block
    const int b    = s >> 8;                    // single b per block (64 | 256)

    // ---------------- Phase 1: means (task-strided, rows ascend in time) ---
#pragma unroll
    for (int it = 0; it < 10; it++) {
        int task = warp + it * 32;              // 0..319
        int rel  = task / 5;
        int t    = task - rel * 5;
        int bc   = s + rel;
        const float* src = (t == 0) ? y : (t == 1) ? x0 : (t == 2) ? x1
                         : (t == 3) ? x2 : x3;
        const float4* p = (const float4*)(src + (size_t)bc * HW);
        float sum = 0.f;
        // Compile-time for it==0 (true) and it>=2 (false); warp-uniform
        // runtime test only at it==1.
        bool do_stash = (it == 0) || (it == 1 && warp < (STASKS - 32));
        if (do_stash) {
            float4* st = stash4 + task * 256;
#pragma unroll
            for (int i = 0; i < 8; i++) {
                float4 v = __ldcs(p + lane + i * 32);   // evict-first
                st[lane + i * 32] = v;
                sum += (v.x + v.y) + (v.z + v.w);
            }
        } else {
#pragma unroll
            for (int i = 0; i < 8; i++) {
                float4 v = p[lane + i * 32];            // keep in L2
                sum += (v.x + v.y) + (v.z + v.w);
            }
        }
#pragma unroll
        for (int o = 16; o; o >>= 1) sum += __shfl_xor_sync(0xFFFFFFFFu, sum, o);
        if (lane == 0) {
            int c = bc & 255;
            g_feats[b * KC + t * NC + c] = sum * (1.0f / 1024.0f);
        }
    }

    // ---------------- Grid barrier (self-resetting, replay-safe) ----------
    __threadfence();
    __syncthreads();
    if (tid == 0) {
        atomicAdd(&g_cnt1, 1u);
        while (*((volatile unsigned*)&g_cnt1) < (unsigned)NBLK) { }
        __threadfence();
        unsigned old = atomicAdd(&g_cnt2, 1u);
        if (old == (unsigned)(NBLK - 1)) {
            g_cnt1 = 0u;
            __threadfence();
            g_cnt2 = 0u;
        }
    }
    __syncthreads();

    // ---------------- Gates: h[b][:] then per-channel gates ----------------
    {
        int m = warp;
        const float4* f4 = (const float4*)(g_feats + b * KC);   // 320 float4
        const float4* w4 = (const float4*)(conv1_w + m * KC);
        float acc = 0.f;
#pragma unroll
        for (int i = 0; i < 10; i++) {
            float4 fv = f4[lane + i * 32];
            float4 wv = w4[lane + i * 32];
            acc += fv.x * wv.x + fv.y * wv.y + fv.z * wv.z + fv.w * wv.w;
        }
#pragma unroll
        for (int o = 16; o; o >>= 1) acc += __shfl_xor_sync(0xFFFFFFFFu, acc, o);
        if (lane == 0) {
            float inv = rsqrtf(bn_var[m] + EPSV);
            float hv  = (acc - bn_mean[m]) * (bn_gamma[m] * inv) + bn_beta[m];
            h_s[m] = fmaxf(hv, 0.f);
        }
    }
    __syncthreads();

    if (tid < BC_PER_BLK) {
        int bc = s + tid;
        int c  = bc & 255;
        float h[MID];
#pragma unroll
        for (int m = 0; m < MID; m++) h[m] = h_s[m];

        float wv[5];
#pragma unroll
        for (int t = 0; t < 5; t++) {
            int j = t * NC + c;
            const float4* w2r = (const float4*)(conv2_w + j * MID);
            float acc = conv2_b[j];
#pragma unroll
            for (int q = 0; q < 8; q++) {
                float4 v = w2r[q];
                acc = fmaf(h[q * 4 + 0], v.x, acc);
                acc = fmaf(h[q * 4 + 1], v.y, acc);
                acc = fmaf(h[q * 4 + 2], v.z, acc);
                acc = fmaf(h[q * 4 + 3], v.w, acc);
            }
            wv[t] = acc;
        }

        sw1[tid] = 1.0f / (1.0f + expf(-wv[0]));
        float mx = fmaxf(fmaxf(wv[1], wv[2]), fmaxf(wv[3], wv[4]));
        float e0 = expf(wv[1] - mx);
        float e1 = expf(wv[2] - mx);
        float e2 = expf(wv[3] - mx);
        float e3 = expf(wv[4] - mx);
        float inv = 1.0f / (e0 + e1 + e2 + e3);
        sw2[0][tid] = e0 * inv;
        sw2[1][tid] = e1 * inv;
        sw2[2][tid] = e2 * inv;
        sw2[3][tid] = e3 * inv;
    }
    __syncthreads();

    // ---------------- Phase 2: gated sum, REVERSE order --------------------
    {
        const int g = tid >> 8;          // 0..3 (row group)
        const int r = tid & 255;         // float4 index within the 1024-row
#pragma unroll
        for (int it = (BC_PER_BLK / 4) - 1; it >= 0; it--) {
            int rel = it * 4 + g;
            int bc  = s + rel;

            float w1 = sw1[rel];
            float wa = sw2[0][rel];
            float wb = sw2[1][rel];
            float wc = sw2[2][rel];
            float wd = sw2[3][rel];

            float4 vy, va, vb, vc, vd;
            if (it < 2) {                 // compile-time: rel = it*4+g < 8
                const float4* st = stash4 + rel * 5 * 256;
                vy = st[0 * 256 + r];
                va = st[1 * 256 + r];
                vb = st[2 * 256 + r];
                vc = st[3 * 256 + r];
                vd = st[4 * 256 + r];
            } else {
                size_t base = (size_t)bc * HW;
                vy = __ldcs((const float4*)(y  + base) + r);
                va = __ldcs((const float4*)(x0 + base) + r);
                vb = __ldcs((const float4*)(x1 + base) + r);
                vc = __ldcs((const float4*)(x2 + base) + r);
                vd = __ldcs((const float4*)(x3 + base) + r);
            }

            float4 res;
            res.x = fmaf(vy.x, w1, fmaf(va.x, wa, fmaf(vb.x, wb, fmaf(vc.x, wc, vd.x * wd))));
            res.y = fmaf(vy.y, w1, fmaf(va.y, wa, fmaf(vb.y, wb, fmaf(vc.y, wc, vd.y * wd))));
            res.z = fmaf(vy.z, w1, fmaf(va.z, wa, fmaf(vb.z, wb, fmaf(vc.z, wc, vd.z * wd))));
            res.w = fmaf(vy.w, w1, fmaf(va.w, wa, fmaf(vb.w, wb, fmaf(vc.w, wc, vd.w * wd))));
            __stcs((float4*)(out + (size_t)bc * HW) + r, res);
        }
    }
}

extern "C" void kernel_launch(void* const* d_in, const int* in_sizes, int n_in,
                              void* d_out, int out_size)
{
    const float* y       = (const float*)d_in[0];
    const float* x0      = (const float*)d_in[1];
    const float* x1      = (const float*)d_in[2];
    const float* x2      = (const float*)d_in[3];
    const float* x3      = (const float*)d_in[4];
    const float* conv1_w = (const float*)d_in[5];
    const float* bn_g    = (const float*)d_in[6];
    const float* bn_b    = (const float*)d_in[7];
    const float* bn_m    = (const float*)d_in[8];
    const float* bn_v    = (const float*)d_in[9];
    const float* conv2_w = (const float*)d_in[10];
    const float* conv2_b = (const float*)d_in[11];
    float* out = (float*)d_out;

    const int dyn_smem = STASKS * 256 * sizeof(float4);   // 163840 B
    cudaFuncSetAttribute(fused_kernel,
                         cudaFuncAttributeMaxDynamicSharedMemorySize, dyn_smem);

    fused_kernel<<<NBLK, 1024, dyn_smem>>>(y, x0, x1, x2, x3,
                                           conv1_w, bn_g, bn_b, bn_m, bn_v,
                                           conv2_w, conv2_b, out);
}